// round 9
// baseline (speedup 1.0000x reference)
#include <cuda_runtime.h>
#include <cuda_bf16.h>
#include <math.h>

// Problem constants (fixed by the dataset)
#define BB 8
#define NN 2000
#define CC 81
#define IOU_THR 0.5f
#define CLASS_OFFSET 100000.0f
#define CAP 96                  // per-(batch,class) bucket capacity (mean ~25, +14 sigma)
#define NROWS (BB * NN)         // 16000
#define NTASK (BB * (CC - 1))   // 640 NMS tasks

#define PREP_BLOCKS 1000        // 1000 blocks * 8 warps * 2 rows = 16000 rows
#define TOTAL_BLOCKS (PREP_BLOCKS + NTASK)   // 1640

// Output layout: concat of reference's 7-tuple, all float32
// (nms_reg, nms_cls, rcnn_reg_adj, probs, reg_out, cls_out, keep)
#define OFF0 0
#define OFF1 (BB*NN*4)
#define OFF2 (OFF1 + BB*NN*2)
#define OFF3 (OFF2 + BB*NN*4)
#define OFF4 (OFF3 + BB*NN*CC)
#define OFF5 (OFF4 + BB*NN*4)
#define OFF6 (OFF5 + BB*NN*CC)

// ---- scratch (device globals; zero-initialized at module load; no allocation) ----
__device__ int                g_cnt[BB*CC];          // bucket counters; nms resets after reading
__device__ unsigned long long g_bkey[BB*CC*CAP];     // composite keys per bucket
__device__ float4             g_bbox[BB*CC*CAP];     // offset boxes per bucket (same slot as key)
__device__ unsigned           g_done;                // prep-complete block counter
__device__ unsigned           g_ndone;               // nms-complete block counter

// reduction input may arrive as int32 or float32; handle both.
__device__ __forceinline__ float read_reduction(const void* p) {
    if (p == nullptr) return 16.0f;
    int iv = *(const int*)p;
    if (iv > 0 && iv < (1 << 20)) return (float)iv;
    return *(const float*)p;
}

// ============================================================
// Fused kernel, 1640 blocks of 256 threads.
//   blocks [0, 1000):   prep — one warp per TWO rows, identical
//                       math to the proven 17.0us version; then
//                       fence + g_done increment.
//   blocks [1000, 1640): one NMS task each. Spin until
//                       g_done == 1000 (spinners only occupy SM
//                       slots freed by retired prep blocks -> no
//                       deadlock, prep runs at full width), then
//                       block-parallel bitmask NMS + fixup.
// Greedy semantics identical to reference (cross-class IoU = 0
// due to CLASS_OFFSET).
// ============================================================
__global__ __launch_bounds__(256)
void fused_kernel(const float* __restrict__ nms_reg,
                  const float* __restrict__ nms_cls,
                  const float* __restrict__ rcnn_reg,
                  const float* __restrict__ rcnn_cls,
                  const void* __restrict__ redp,
                  float* __restrict__ out)
{
    const int tid  = threadIdx.x;
    const int lane = tid & 31;
    const int wib  = tid >> 5;

    if (blockIdx.x < PREP_BLOCKS) {
        // ==================== PREP ====================
        const int gw   = blockIdx.x * 8 + wib;
        const int row0 = gw * 2;
        const int row1 = row0 + 1;

        const bool has2 = (lane < CC - 64);
        const float* cl0 = rcnn_cls + (size_t)row0 * CC;
        const float* cl1 = cl0 + CC;

        float a0 = cl0[lane];
        float a1 = cl0[lane + 32];
        float a2 = has2 ? cl0[lane + 64] : -INFINITY;
        float b0 = cl1[lane];
        float b1 = cl1[lane + 32];
        float b2 = has2 ? cl1[lane + 64] : -INFINITY;

        float mA = fmaxf(a0, fmaxf(a1, a2));
        float mB = fmaxf(b0, fmaxf(b1, b2));
        #pragma unroll
        for (int o = 16; o; o >>= 1) {
            mA = fmaxf(mA, __shfl_xor_sync(0xFFFFFFFFu, mA, o));
            mB = fmaxf(mB, __shfl_xor_sync(0xFFFFFFFFu, mB, o));
        }

        float eA0 = expf(a0 - mA), eA1 = expf(a1 - mA), eA2 = has2 ? expf(a2 - mA) : 0.0f;
        float eB0 = expf(b0 - mB), eB1 = expf(b1 - mB), eB2 = has2 ? expf(b2 - mB) : 0.0f;
        float sA = eA0 + eA1 + eA2;
        float sB = eB0 + eB1 + eB2;
        #pragma unroll
        for (int o = 16; o; o >>= 1) {
            sA += __shfl_xor_sync(0xFFFFFFFFu, sA, o);
            sB += __shfl_xor_sync(0xFFFFFFFFu, sB, o);
        }

        float pA0 = eA0 / sA, pA1 = eA1 / sA, pA2 = eA2 / sA;
        float pB0 = eB0 / sB, pB1 = eB1 / sB, pB2 = eB2 / sB;

        float* poA = out + OFF3 + (size_t)row0 * CC;
        float* poB = poA + CC;
        poA[lane]      = pA0;
        poA[lane + 32] = pA1;
        if (has2) poA[lane + 64] = pA2;
        poB[lane]      = pB0;
        poB[lane + 32] = pB1;
        if (has2) poB[lane + 64] = pB2;

        float bpA = pA0; int biA = lane;
        if (pA1 > bpA) { bpA = pA1; biA = lane + 32; }
        if (has2 && pA2 > bpA) { bpA = pA2; biA = lane + 64; }
        float bpB = pB0; int biB = lane;
        if (pB1 > bpB) { bpB = pB1; biB = lane + 32; }
        if (has2 && pB2 > bpB) { bpB = pB2; biB = lane + 64; }
        #pragma unroll
        for (int o = 16; o; o >>= 1) {
            float opA = __shfl_xor_sync(0xFFFFFFFFu, bpA, o);
            int   oiA = __shfl_xor_sync(0xFFFFFFFFu, biA, o);
            if (opA > bpA || (opA == bpA && oiA < biA)) { bpA = opA; biA = oiA; }
            float opB = __shfl_xor_sync(0xFFFFFFFFu, bpB, o);
            int   oiB = __shfl_xor_sync(0xFFFFFFFFu, biB, o);
            if (opB > bpB || (opB == bpB && oiB < biB)) { bpB = opB; biB = oiB; }
        }

        const float kA = (biA != 0) ? 1.0f : 0.0f;
        const float kB = (biB != 0) ? 1.0f : 0.0f;

        float* coA = out + OFF5 + (size_t)row0 * CC;
        float* coB = coA + CC;
        coA[lane]      = pA0 * kA;
        coA[lane + 32] = pA1 * kA;
        if (has2) coA[lane + 64] = pA2 * kA;
        coB[lane]      = pB0 * kB;
        coB[lane + 32] = pB1 * kB;
        if (has2) coB[lane + 64] = pB2 * kB;

        if (lane < 2) {
            const int   row = (lane == 0) ? row0 : row1;
            const int   cls = (lane == 0) ? biA  : biB;
            const float bp  = (lane == 0) ? bpA  : bpB;
            const float k   = (lane == 0) ? kA   : kB;
            const float red = read_reduction(redp);

            float4 nr = ((const float4*)nms_reg)[row];
            float rt = floorf(nr.x * red) / red;
            float rl = floorf(nr.y * red) / red;
            float rb = ceilf(nr.z * red) / red;
            float rr = ceilf(nr.w * red) / red;

            float4 rg = ((const float4*)rcnn_reg)[row];
            float4 adj;
            adj.x = rg.x + rt; adj.y = rg.y + rl; adj.z = rg.z + rb; adj.w = rg.w + rr;
            ((float4*)(out + OFF2))[row] = adj;

            float4 ro;
            ro.x = adj.x * k; ro.y = adj.y * k; ro.z = adj.z * k; ro.w = adj.w * k;
            ((float4*)(out + OFF4))[row] = ro;

            ((float4*)(out + OFF0))[row] = nr;
            ((float2*)(out + OFF1))[row] = ((const float2*)nms_cls)[row];

            out[OFF6 + row] = k;

            if (cls != 0) {
                unsigned sb = __float_as_uint(bp);
                unsigned so = (sb & 0x80000000u) ? ~sb : (sb | 0x80000000u);
                unsigned sdesc = ~so;
                int b = row / NN, n = row % NN;
                unsigned long long key = ((unsigned long long)sdesc << 32)
                                       | (unsigned long long)(unsigned)n;
                int bc = b * CC + cls;
                int pos = atomicAdd(&g_cnt[bc], 1);
                if (pos < CAP) {
                    size_t slot = (size_t)bc * CAP + pos;
                    g_bkey[slot] = key;
                    float off = (float)cls * CLASS_OFFSET;
                    float4 ob;
                    ob.x = adj.x + off; ob.y = adj.y + off;
                    ob.z = adj.z + off; ob.w = adj.w + off;
                    g_bbox[slot] = ob;
                }
            }
        }

        // publish prep completion
        __syncthreads();
        if (tid == 0) {
            __threadfence();
            atomicAdd(&g_done, 1u);
        }
        return;
    }

    // ==================== NMS (blocks 1000..1639) ====================
    const int task = blockIdx.x - PREP_BLOCKS;   // 0..639
    const int wid  = wib;

    const int b  = task / (CC - 1);
    const int c  = task % (CC - 1) + 1;
    const int bc = b * CC + c;

    __shared__ unsigned long long s_key[CAP];
    __shared__ float4             s_box[CAP];
    __shared__ unsigned short     s_sid[CAP];
    __shared__ uint4              s_rm [CAP];
    __shared__ unsigned           s_keepw[3];
    __shared__ int                s_anysup;

    // wait until every prep block has published its writes
    if (tid == 0) {
        while (*((volatile unsigned*)&g_done) < (unsigned)PREP_BLOCKS) { __nanosleep(64); }
        __threadfence();
        s_anysup = 0;
    }
    __syncthreads();

    // parallel bucket loads (L2; skip L1 — data written by other SMs this launch)
    const size_t base = (size_t)bc * CAP;
    unsigned long long mykey = 0ull;
    float4 mybox;
    if (tid < CAP) {
        mykey = __ldcg(&g_bkey[base + tid]);
        mybox = __ldcg(&g_bbox[base + tid]);
    }
    int n = __ldcg(&g_cnt[bc]);
    if (n > CAP) n = CAP;

    if (tid < n) s_key[tid] = mykey;
    __syncthreads();
    if (tid == 0) g_cnt[bc] = 0;                 // reset for next replay

    if (n > 0) {
        // rank sort + box placement (keys unique via idx low bits)
        if (tid < n) {
            int rank = 0;
            for (int kk = 0; kk < n; kk++) rank += (s_key[kk] < mykey);
            s_sid[rank] = (unsigned short)(mykey & 0xFFFFFFFFu);
            s_box[rank] = mybox;
        }
        __syncthreads();

        // ---- Phase B: suppression matrix, rows split across warps ----
        {
            float4 bx0, bx1, bx2;
            float ar0 = 0.0f, ar1 = 0.0f, ar2 = 0.0f;
            if (lane < n)      { bx0 = s_box[lane];      ar0 = (bx0.z - bx0.x) * (bx0.w - bx0.y); }
            if (lane + 32 < n) { bx1 = s_box[lane + 32]; ar1 = (bx1.z - bx1.x) * (bx1.w - bx1.y); }
            if (lane + 64 < n) { bx2 = s_box[lane + 64]; ar2 = (bx2.z - bx2.x) * (bx2.w - bx2.y); }

            bool any = false;
            for (int i = wid; i < n - 1; i += 8) {
                float4 bi = s_box[i];
                float areai = (bi.z - bi.x) * (bi.w - bi.y);

                bool sup0 = false, sup1 = false, sup2 = false;
                {
                    int j = lane;
                    if (j < n && j > i) {
                        float it = fmaxf(bi.x, bx0.x);
                        float il = fmaxf(bi.y, bx0.y);
                        float ib = fminf(bi.z, bx0.z);
                        float ir = fminf(bi.w, bx0.w);
                        float inter = fmaxf(ib - it, 0.0f) * fmaxf(ir - il, 0.0f);
                        float uni = areai + ar0 - inter;
                        float iou = inter / fmaxf(uni, 1e-9f);
                        sup0 = (iou > IOU_THR);
                    }
                }
                unsigned w0 = __ballot_sync(0xFFFFFFFFu, sup0);
                unsigned w1 = 0, w2 = 0;
                if (n > 32) {
                    int j = lane + 32;
                    if (j < n && j > i) {
                        float it = fmaxf(bi.x, bx1.x);
                        float il = fmaxf(bi.y, bx1.y);
                        float ib = fminf(bi.z, bx1.z);
                        float ir = fminf(bi.w, bx1.w);
                        float inter = fmaxf(ib - it, 0.0f) * fmaxf(ir - il, 0.0f);
                        float uni = areai + ar1 - inter;
                        float iou = inter / fmaxf(uni, 1e-9f);
                        sup1 = (iou > IOU_THR);
                    }
                    w1 = __ballot_sync(0xFFFFFFFFu, sup1);
                }
                if (n > 64) {
                    int j = lane + 64;
                    if (j < n && j > i) {
                        float it = fmaxf(bi.x, bx2.x);
                        float il = fmaxf(bi.y, bx2.y);
                        float ib = fminf(bi.z, bx2.z);
                        float ir = fminf(bi.w, bx2.w);
                        float inter = fmaxf(ib - it, 0.0f) * fmaxf(ir - il, 0.0f);
                        float uni = areai + ar2 - inter;
                        float iou = inter / fmaxf(uni, 1e-9f);
                        sup2 = (iou > IOU_THR);
                    }
                    w2 = __ballot_sync(0xFFFFFFFFu, sup2);
                }
                if (lane == 0) {
                    uint4 rm; rm.x = w0; rm.y = w1; rm.z = w2; rm.w = 0;
                    s_rm[i] = rm;
                    if ((w0 | w1 | w2) != 0u) any = true;
                }
            }
            if (any) s_anysup = 1;     // benign race; only 1s written
        }
        __syncthreads();

        if (s_anysup != 0) {
            // ---- Phase C: serial bit resolution (warp 0, registers) ----
            if (wid == 0) {
                unsigned k0, k1, k2;
                k0 = (n >= 32) ? 0xFFFFFFFFu : ((1u << n) - 1u);
                k1 = (n >= 64) ? 0xFFFFFFFFu : ((n > 32) ? ((1u << (n - 32)) - 1u) : 0u);
                k2 = (n > 64) ? ((n >= 96) ? 0xFFFFFFFFu : ((1u << (n - 64)) - 1u)) : 0u;

                for (int i = 0; i < n - 1; i++) {
                    unsigned word = (i < 32) ? k0 : ((i < 64) ? k1 : k2);
                    if ((word >> (i & 31)) & 1u) {
                        uint4 rm = s_rm[i];
                        k0 &= ~rm.x; k1 &= ~rm.y; k2 &= ~rm.z;
                    }
                }
                if (lane == 0) { s_keepw[0] = k0; s_keepw[1] = k1; s_keepw[2] = k2; }
            }
            __syncthreads();

            // ---- Phase D: fixup suppressed rows, split across warps ----
            for (int i = wid; i < n; i += 8) {
                unsigned word = s_keepw[i >> 5];
                if (!((word >> (i & 31)) & 1u)) {
                    int row = b * NN + (int)s_sid[i];
                    float* co = out + OFF5 + (size_t)row * CC;
                    co[lane]      = 0.0f;
                    co[lane + 32] = 0.0f;
                    if (lane < CC - 64) co[lane + 64] = 0.0f;
                    if (lane == 0) {
                        float4 z; z.x = 0.0f; z.y = 0.0f; z.z = 0.0f; z.w = 0.0f;
                        ((float4*)(out + OFF4))[row] = z;
                        out[OFF6 + row] = 0.0f;
                    }
                }
            }
        }
    }

    // replay-reset (every nms block reaches this; last one resets flags)
    __syncthreads();
    if (tid == 0) {
        unsigned r = atomicAdd(&g_ndone, 1u);
        if (r == (unsigned)(NTASK - 1)) {
            atomicExch(&g_ndone, 0u);
            atomicExch(&g_done, 0u);
        }
    }
}

extern "C" void kernel_launch(void* const* d_in, const int* in_sizes, int n_in,
                              void* d_out, int out_size)
{
    const float* nms_reg  = (const float*)d_in[0];
    const float* nms_cls  = (const float*)d_in[1];
    const float* rcnn_reg = (const float*)d_in[2];
    const float* rcnn_cls = (const float*)d_in[3];
    const void*  redp     = (n_in >= 5) ? d_in[4] : nullptr;
    float* out = (float*)d_out;
    (void)in_sizes; (void)out_size;

    fused_kernel<<<TOTAL_BLOCKS, 256>>>(nms_reg, nms_cls, rcnn_reg, rcnn_cls, redp, out);
}

// round 10
// speedup vs baseline: 1.2593x; 1.2593x over previous
#include <cuda_runtime.h>
#include <cuda_bf16.h>
#include <math.h>

// Problem constants (fixed by the dataset)
#define BB 8
#define NN 2000
#define CC 81
#define IOU_THR 0.5f
#define CLASS_OFFSET 100000.0f
#define CAP 96                  // per-(batch,class) bucket capacity (mean ~25, +14 sigma)
#define NROWS (BB * NN)         // 16000
#define NTASK (BB * (CC - 1))   // 640 NMS tasks

// Output layout: concat of reference's 7-tuple, all float32
// (nms_reg, nms_cls, rcnn_reg_adj, probs, reg_out, cls_out, keep)
#define OFF0 0
#define OFF1 (BB*NN*4)
#define OFF2 (OFF1 + BB*NN*2)
#define OFF3 (OFF2 + BB*NN*4)
#define OFF4 (OFF3 + BB*NN*CC)
#define OFF5 (OFF4 + BB*NN*4)
#define OFF6 (OFF5 + BB*NN*CC)

// ---- scratch (device globals; zero-initialized at module load; no allocation) ----
__device__ int                g_cnt[BB*CC];          // bucket counters; nms resets after reading
__device__ unsigned long long g_bkey[BB*CC*CAP];     // composite keys per bucket
__device__ float4             g_bbox[BB*CC*CAP];     // offset boxes per bucket (same slot as key)

// reduction input may arrive as int32 or float32; handle both.
__device__ __forceinline__ float read_reduction(const void* p) {
    if (p == nullptr) return 16.0f;
    int iv = *(const int*)p;
    if (iv > 0 && iv < (1 << 20)) return (float)iv;
    return *(const float*)p;
}

// ============================================================
// Kernel 1: per-row prep, one warp per TWO rows (ILP x2).
// Identical math to the proven 17.0us version. Triggers
// programmatic launch completion at block end so the dependent
// NMS kernel can pre-launch and park.
// ============================================================
__global__ __launch_bounds__(256)
void prep_kernel(const float* __restrict__ nms_reg,
                 const float* __restrict__ nms_cls,
                 const float* __restrict__ rcnn_reg,
                 const float* __restrict__ rcnn_cls,
                 const void* __restrict__ redp,
                 float* __restrict__ out)
{
    const int gw   = (blockIdx.x * blockDim.x + threadIdx.x) >> 5;
    const int lane = threadIdx.x & 31;
    const int row0 = gw * 2;
    if (row0 < NROWS) {
        const int row1 = row0 + 1;

        const bool has2 = (lane < CC - 64);
        const float* cl0 = rcnn_cls + (size_t)row0 * CC;
        const float* cl1 = cl0 + CC;

        float a0 = cl0[lane];
        float a1 = cl0[lane + 32];
        float a2 = has2 ? cl0[lane + 64] : -INFINITY;
        float b0 = cl1[lane];
        float b1 = cl1[lane + 32];
        float b2 = has2 ? cl1[lane + 64] : -INFINITY;

        float mA = fmaxf(a0, fmaxf(a1, a2));
        float mB = fmaxf(b0, fmaxf(b1, b2));
        #pragma unroll
        for (int o = 16; o; o >>= 1) {
            mA = fmaxf(mA, __shfl_xor_sync(0xFFFFFFFFu, mA, o));
            mB = fmaxf(mB, __shfl_xor_sync(0xFFFFFFFFu, mB, o));
        }

        float eA0 = expf(a0 - mA), eA1 = expf(a1 - mA), eA2 = has2 ? expf(a2 - mA) : 0.0f;
        float eB0 = expf(b0 - mB), eB1 = expf(b1 - mB), eB2 = has2 ? expf(b2 - mB) : 0.0f;
        float sA = eA0 + eA1 + eA2;
        float sB = eB0 + eB1 + eB2;
        #pragma unroll
        for (int o = 16; o; o >>= 1) {
            sA += __shfl_xor_sync(0xFFFFFFFFu, sA, o);
            sB += __shfl_xor_sync(0xFFFFFFFFu, sB, o);
        }

        float pA0 = eA0 / sA, pA1 = eA1 / sA, pA2 = eA2 / sA;
        float pB0 = eB0 / sB, pB1 = eB1 / sB, pB2 = eB2 / sB;

        float* poA = out + OFF3 + (size_t)row0 * CC;
        float* poB = poA + CC;
        poA[lane]      = pA0;
        poA[lane + 32] = pA1;
        if (has2) poA[lane + 64] = pA2;
        poB[lane]      = pB0;
        poB[lane + 32] = pB1;
        if (has2) poB[lane + 64] = pB2;

        float bpA = pA0; int biA = lane;
        if (pA1 > bpA) { bpA = pA1; biA = lane + 32; }
        if (has2 && pA2 > bpA) { bpA = pA2; biA = lane + 64; }
        float bpB = pB0; int biB = lane;
        if (pB1 > bpB) { bpB = pB1; biB = lane + 32; }
        if (has2 && pB2 > bpB) { bpB = pB2; biB = lane + 64; }
        #pragma unroll
        for (int o = 16; o; o >>= 1) {
            float opA = __shfl_xor_sync(0xFFFFFFFFu, bpA, o);
            int   oiA = __shfl_xor_sync(0xFFFFFFFFu, biA, o);
            if (opA > bpA || (opA == bpA && oiA < biA)) { bpA = opA; biA = oiA; }
            float opB = __shfl_xor_sync(0xFFFFFFFFu, bpB, o);
            int   oiB = __shfl_xor_sync(0xFFFFFFFFu, biB, o);
            if (opB > bpB || (opB == bpB && oiB < biB)) { bpB = opB; biB = oiB; }
        }

        const float kA = (biA != 0) ? 1.0f : 0.0f;
        const float kB = (biB != 0) ? 1.0f : 0.0f;

        float* coA = out + OFF5 + (size_t)row0 * CC;
        float* coB = coA + CC;
        coA[lane]      = pA0 * kA;
        coA[lane + 32] = pA1 * kA;
        if (has2) coA[lane + 64] = pA2 * kA;
        coB[lane]      = pB0 * kB;
        coB[lane + 32] = pB1 * kB;
        if (has2) coB[lane + 64] = pB2 * kB;

        if (lane < 2) {
            const int   row = (lane == 0) ? row0 : row1;
            const int   cls = (lane == 0) ? biA  : biB;
            const float bp  = (lane == 0) ? bpA  : bpB;
            const float k   = (lane == 0) ? kA   : kB;
            const float red = read_reduction(redp);

            float4 nr = ((const float4*)nms_reg)[row];
            float rt = floorf(nr.x * red) / red;
            float rl = floorf(nr.y * red) / red;
            float rb = ceilf(nr.z * red) / red;
            float rr = ceilf(nr.w * red) / red;

            float4 rg = ((const float4*)rcnn_reg)[row];
            float4 adj;
            adj.x = rg.x + rt; adj.y = rg.y + rl; adj.z = rg.z + rb; adj.w = rg.w + rr;
            ((float4*)(out + OFF2))[row] = adj;

            float4 ro;
            ro.x = adj.x * k; ro.y = adj.y * k; ro.z = adj.z * k; ro.w = adj.w * k;
            ((float4*)(out + OFF4))[row] = ro;

            ((float4*)(out + OFF0))[row] = nr;
            ((float2*)(out + OFF1))[row] = ((const float2*)nms_cls)[row];

            out[OFF6 + row] = k;

            if (cls != 0) {
                unsigned sb = __float_as_uint(bp);
                unsigned so = (sb & 0x80000000u) ? ~sb : (sb | 0x80000000u);
                unsigned sdesc = ~so;
                int b = row / NN, n = row % NN;
                unsigned long long key = ((unsigned long long)sdesc << 32)
                                       | (unsigned long long)(unsigned)n;
                int bc = b * CC + cls;
                int pos = atomicAdd(&g_cnt[bc], 1);
                if (pos < CAP) {
                    size_t slot = (size_t)bc * CAP + pos;
                    g_bkey[slot] = key;
                    float off = (float)cls * CLASS_OFFSET;
                    float4 ob;
                    ob.x = adj.x + off; ob.y = adj.y + off;
                    ob.z = adj.z + off; ob.w = adj.w + off;
                    g_bbox[slot] = ob;
                }
            }
        }
    }

    // allow the dependent NMS kernel to start launching
    cudaTriggerProgrammaticLaunchCompletion();
}

// ============================================================
// Kernel 2: block-per-task bitmask NMS (256 threads = 8 warps),
// launched with programmatic dependent launch (parks at
// cudaGridDependencySynchronize until prep completes).
//  A: speculative parallel bucket loads, rank sort.
//  B: suppression matrix rows split across warps; active-row
//     bitmask accumulated (rows whose mask is nonzero).
//  C: ffs-scan resolution over ACTIVE rows only, redundantly in
//     every warp (registers; no extra barrier).
//  D: fixup suppressed rows, split across warps.
// Greedy semantics identical to reference (cross-class IoU = 0).
// ============================================================
#define NTPB 256
__global__ __launch_bounds__(NTPB)
void nms_kernel(float* __restrict__ out)
{
    const int task = blockIdx.x;                 // 0..639
    const int tid  = threadIdx.x;
    const int lane = tid & 31;
    const int wid  = tid >> 5;                   // 0..7

    const int b  = task / (CC - 1);
    const int c  = task % (CC - 1) + 1;
    const int bc = b * CC + c;

    __shared__ unsigned long long s_key[CAP];
    __shared__ float4             s_box[CAP];
    __shared__ unsigned short     s_sid[CAP];
    __shared__ uint4              s_rm [CAP];
    __shared__ unsigned           s_active[3];

    // wait for prep's writes to be visible (PDL)
    cudaGridDependencySynchronize();

    // ---- speculative parallel loads (independent; all overlap) ----
    const size_t base = (size_t)bc * CAP;
    unsigned long long mykey = 0ull;
    float4 mybox;
    if (tid < CAP) {
        mykey = __ldcg(&g_bkey[base + tid]);
        mybox = __ldcg(&g_bbox[base + tid]);
    }
    int n = __ldcg(&g_cnt[bc]);
    if (n > CAP) n = CAP;

    if (tid < 3) s_active[tid] = 0u;
    if (tid < n) s_key[tid] = mykey;
    __syncthreads();
    if (tid == 0) g_cnt[bc] = 0;                 // reset for next replay

    if (n <= 0) return;

    // rank sort + box placement (keys unique via idx low bits)
    if (tid < n) {
        int rank = 0;
        for (int kk = 0; kk < n; kk++) rank += (s_key[kk] < mykey);
        s_sid[rank] = (unsigned short)(mykey & 0xFFFFFFFFu);
        s_box[rank] = mybox;
    }
    __syncthreads();

    // ---- Phase B: suppression matrix, rows split across warps ----
    {
        float4 bx0, bx1, bx2;
        float ar0 = 0.0f, ar1 = 0.0f, ar2 = 0.0f;
        if (lane < n)      { bx0 = s_box[lane];      ar0 = (bx0.z - bx0.x) * (bx0.w - bx0.y); }
        if (lane + 32 < n) { bx1 = s_box[lane + 32]; ar1 = (bx1.z - bx1.x) * (bx1.w - bx1.y); }
        if (lane + 64 < n) { bx2 = s_box[lane + 64]; ar2 = (bx2.z - bx2.x) * (bx2.w - bx2.y); }

        for (int i = wid; i < n - 1; i += 8) {
            float4 bi = s_box[i];
            float areai = (bi.z - bi.x) * (bi.w - bi.y);

            bool sup0 = false, sup1 = false, sup2 = false;
            {
                int j = lane;
                if (j < n && j > i) {
                    float it = fmaxf(bi.x, bx0.x);
                    float il = fmaxf(bi.y, bx0.y);
                    float ib = fminf(bi.z, bx0.z);
                    float ir = fminf(bi.w, bx0.w);
                    float inter = fmaxf(ib - it, 0.0f) * fmaxf(ir - il, 0.0f);
                    float uni = areai + ar0 - inter;
                    float iou = inter / fmaxf(uni, 1e-9f);
                    sup0 = (iou > IOU_THR);
                }
            }
            unsigned w0 = __ballot_sync(0xFFFFFFFFu, sup0);
            unsigned w1 = 0, w2 = 0;
            if (n > 32) {
                int j = lane + 32;
                if (j < n && j > i) {
                    float it = fmaxf(bi.x, bx1.x);
                    float il = fmaxf(bi.y, bx1.y);
                    float ib = fminf(bi.z, bx1.z);
                    float ir = fminf(bi.w, bx1.w);
                    float inter = fmaxf(ib - it, 0.0f) * fmaxf(ir - il, 0.0f);
                    float uni = areai + ar1 - inter;
                    float iou = inter / fmaxf(uni, 1e-9f);
                    sup1 = (iou > IOU_THR);
                }
                w1 = __ballot_sync(0xFFFFFFFFu, sup1);
            }
            if (n > 64) {
                int j = lane + 64;
                if (j < n && j > i) {
                    float it = fmaxf(bi.x, bx2.x);
                    float il = fmaxf(bi.y, bx2.y);
                    float ib = fminf(bi.z, bx2.z);
                    float ir = fminf(bi.w, bx2.w);
                    float inter = fmaxf(ib - it, 0.0f) * fmaxf(ir - il, 0.0f);
                    float uni = areai + ar2 - inter;
                    float iou = inter / fmaxf(uni, 1e-9f);
                    sup2 = (iou > IOU_THR);
                }
                w2 = __ballot_sync(0xFFFFFFFFu, sup2);
            }
            if (lane == 0) {
                uint4 rm; rm.x = w0; rm.y = w1; rm.z = w2; rm.w = 0;
                s_rm[i] = rm;
                if ((w0 | w1 | w2) != 0u)
                    atomicOr(&s_active[i >> 5], 1u << (i & 31));
            }
        }
    }
    __syncthreads();

    // ---- Phase C: ffs-scan over ACTIVE rows only (every warp, registers) ----
    unsigned a0 = s_active[0], a1 = s_active[1], a2 = s_active[2];
    if ((a0 | a1 | a2) == 0u) return;    // no suppression anywhere: outputs final

    unsigned k0, k1, k2;
    k0 = (n >= 32) ? 0xFFFFFFFFu : ((1u << n) - 1u);
    k1 = (n >= 64) ? 0xFFFFFFFFu : ((n > 32) ? ((1u << (n - 32)) - 1u) : 0u);
    k2 = (n > 64) ? ((n >= 96) ? 0xFFFFFFFFu : ((1u << (n - 64)) - 1u)) : 0u;

    for (;;) {
        unsigned c0 = a0 & k0, c1 = a1 & k1, c2 = a2 & k2;
        int i;
        if (c0)      i = __ffs(c0) - 1;
        else if (c1) i = 31 + __ffs(c1);
        else if (c2) i = 63 + __ffs(c2);
        else break;
        uint4 rm = s_rm[i];                      // smem broadcast (read-only)
        k0 &= ~rm.x; k1 &= ~rm.y; k2 &= ~rm.z;
        if (i < 32)      a0 &= ~(1u << i);
        else if (i < 64) a1 &= ~(1u << (i - 32));
        else             a2 &= ~(1u << (i - 64));
    }
    // rm[i] has only bits > i set, so the ascending ffs order reproduces the
    // reference greedy order exactly; rows with rm==0 never change keep state.

    // ---- Phase D: fixup suppressed rows, split across warps ----
    for (int i = wid; i < n; i += 8) {
        unsigned word = (i < 32) ? k0 : ((i < 64) ? k1 : k2);
        if (!((word >> (i & 31)) & 1u)) {
            int row = b * NN + (int)s_sid[i];
            float* co = out + OFF5 + (size_t)row * CC;
            co[lane]      = 0.0f;
            co[lane + 32] = 0.0f;
            if (lane < CC - 64) co[lane + 64] = 0.0f;
            if (lane == 0) {
                float4 z; z.x = 0.0f; z.y = 0.0f; z.z = 0.0f; z.w = 0.0f;
                ((float4*)(out + OFF4))[row] = z;
                out[OFF6 + row] = 0.0f;
            }
        }
    }
}

extern "C" void kernel_launch(void* const* d_in, const int* in_sizes, int n_in,
                              void* d_out, int out_size)
{
    const float* nms_reg  = (const float*)d_in[0];
    const float* nms_cls  = (const float*)d_in[1];
    const float* rcnn_reg = (const float*)d_in[2];
    const float* rcnn_cls = (const float*)d_in[3];
    const void*  redp     = (n_in >= 5) ? d_in[4] : nullptr;
    float* out = (float*)d_out;
    (void)in_sizes; (void)out_size;

    const int warps = NROWS / 2;
    const int tpb = 256;
    const int blocks = (warps * 32 + tpb - 1) / tpb;   // 1000
    prep_kernel<<<blocks, tpb>>>(nms_reg, nms_cls, rcnn_reg, rcnn_cls, redp, out);

    // NMS with programmatic dependent launch: pre-launches and parks at
    // cudaGridDependencySynchronize(), hiding launch/distribution latency
    // behind prep's execution.
    cudaLaunchConfig_t cfg = {};
    cfg.gridDim  = dim3(NTASK, 1, 1);
    cfg.blockDim = dim3(NTPB, 1, 1);
    cfg.dynamicSmemBytes = 0;
    cudaLaunchAttribute attrs[1];
    attrs[0].id = cudaLaunchAttributeProgrammaticStreamSerialization;
    attrs[0].val.programmaticStreamSerializationAllowed = 1;
    cfg.attrs = attrs;
    cfg.numAttrs = 1;
    cudaLaunchKernelEx(&cfg, nms_kernel, out);
}